// round 3
// baseline (speedup 1.0000x reference)
#include <cuda_runtime.h>
#include <math.h>

// Problem constants
#define SEQ 2048
#define BATCH 2
#define EMB 1024
#define HEADS 16
#define HDIM 64
#define ROWS (SEQ * BATCH)   // 4096

// Scratch (allocation-free rule: __device__ globals)
__device__ float g_xnorm[(size_t)ROWS * EMB];
__device__ float g_qkv[(size_t)ROWS * EMB];
__device__ float g_u[(size_t)ROWS * EMB];
__device__ float g_attn[(size_t)ROWS * EMB];

__device__ __forceinline__ float silu_f(float x) {
    return x / (1.0f + expf(-x));
}

// ---------------------------------------------------------------------------
// Kernel 1: LayerNorm. One block (256 thr) per row of 1024 floats.
// ---------------------------------------------------------------------------
__global__ void ln_kernel(const float* __restrict__ src,
                          const float* __restrict__ gamma,
                          const float* __restrict__ beta) {
    int row = blockIdx.x;
    int t = threadIdx.x;
    const float4* x4 = (const float4*)(src + (size_t)row * EMB);
    float4 v = x4[t];
    float s = v.x + v.y + v.z + v.w;
    float q = v.x * v.x + v.y * v.y + v.z * v.z + v.w * v.w;
    #pragma unroll
    for (int o = 16; o > 0; o >>= 1) {
        s += __shfl_xor_sync(0xFFFFFFFFu, s, o);
        q += __shfl_xor_sync(0xFFFFFFFFu, q, o);
    }
    __shared__ float ss[8], sq[8];
    int w = t >> 5, l = t & 31;
    if (l == 0) { ss[w] = s; sq[w] = q; }
    __syncthreads();
    float st = 0.f, qt = 0.f;
    #pragma unroll
    for (int i = 0; i < 8; i++) { st += ss[i]; qt += sq[i]; }
    float mu = st * (1.0f / EMB);
    float var = qt * (1.0f / EMB) - mu * mu;
    float inv = rsqrtf(var + 1e-5f);
    float4 gg = ((const float4*)gamma)[t];
    float4 bb = ((const float4*)beta)[t];
    float4 o;
    o.x = (v.x - mu) * inv * gg.x + bb.x;
    o.y = (v.y - mu) * inv * gg.y + bb.y;
    o.z = (v.z - mu) * inv * gg.z + bb.z;
    o.w = (v.w - mu) * inv * gg.w + bb.w;
    ((float4*)(g_xnorm + (size_t)row * EMB))[t] = o;
}

// ---------------------------------------------------------------------------
// Kernel 2: in_proj GEMM + bias + SiLU, split into qkv / u.
// C[m,n] = sum_k xnorm[m,k] * W[n,k]   (M=4096, N=2048, K=1024)
// 64x64 tile, BK=16, 256 threads, 4x4 microtile.
// ---------------------------------------------------------------------------
__global__ void inproj_kernel(const float* __restrict__ W,
                              const float* __restrict__ bias) {
    __shared__ float As[16][68];
    __shared__ float Bs[16][68];
    int bm = blockIdx.y * 64;
    int bn = blockIdx.x * 64;
    int tid = threadIdx.x;
    int lr = tid >> 2;        // 0..63
    int lc = tid & 3;         // float4 group 0..3
    int tm = (tid >> 4) << 2; // 0..60
    int tn = (tid & 15) << 2; // 0..60
    float acc[4][4] = {};
    for (int k0 = 0; k0 < EMB; k0 += 16) {
        float4 a = *(const float4*)(g_xnorm + (size_t)(bm + lr) * EMB + k0 + lc * 4);
        float4 b = *(const float4*)(W + (size_t)(bn + lr) * EMB + k0 + lc * 4);
        As[lc * 4 + 0][lr] = a.x; As[lc * 4 + 1][lr] = a.y;
        As[lc * 4 + 2][lr] = a.z; As[lc * 4 + 3][lr] = a.w;
        Bs[lc * 4 + 0][lr] = b.x; Bs[lc * 4 + 1][lr] = b.y;
        Bs[lc * 4 + 2][lr] = b.z; Bs[lc * 4 + 3][lr] = b.w;
        __syncthreads();
        #pragma unroll
        for (int k = 0; k < 16; k++) {
            float4 ra = *(const float4*)&As[k][tm];
            float4 rb = *(const float4*)&Bs[k][tn];
            float pa[4] = {ra.x, ra.y, ra.z, ra.w};
            float pb[4] = {rb.x, rb.y, rb.z, rb.w};
            #pragma unroll
            for (int i = 0; i < 4; i++)
                #pragma unroll
                for (int j = 0; j < 4; j++)
                    acc[i][j] += pa[i] * pb[j];
        }
        __syncthreads();
    }
    #pragma unroll
    for (int i = 0; i < 4; i++) {
        int m = bm + tm + i;
        #pragma unroll
        for (int j = 0; j < 4; j++) {
            int n = bn + tn + j;
            float v = silu_f(acc[i][j] + bias[n]);
            if (n < EMB) g_qkv[(size_t)m * EMB + n] = v;
            else         g_u[(size_t)m * EMB + (n - EMB)] = v;
        }
    }
}

// ---------------------------------------------------------------------------
// Kernel 3: fused causal SiLU-attention. Block = (b,h, q-tile of 64 rows).
// For kt <= qt: S = Q @ K^T / 8 ; W = mask(silu(S)) ; O += W @ V   (V == K)
// Dynamic smem: Qt[d][i], Kt[d][j], Vs[j][d], Ws[j][i]  each 64x68 floats.
// ---------------------------------------------------------------------------
__global__ void attn_kernel() {
    extern __shared__ float smem[];
    float* Qt = smem;                 // [64][68] d-major
    float* Kt = Qt + 64 * 68;         // [64][68] d-major
    float* Vs = Kt + 64 * 68;         // [64][68] j-major
    float* Ws = Vs + 64 * 68;         // [64][68] j-major (W transposed)

    int qt = blockIdx.x;              // 0..31
    int bh = blockIdx.y;              // 0..31
    int b = bh >> 4, h = bh & 15;
    int tid = threadIdx.x;
    int tm = (tid >> 4) << 2;
    int tn = (tid & 15) << 2;
    int lrow = tid >> 4;              // 0..15
    int dg = (tid & 15) << 2;         // d group (float4)

    // Load Q tile (transposed into d-major)
    #pragma unroll
    for (int rr = 0; rr < 4; rr++) {
        int i = lrow + rr * 16;
        int s = qt * 64 + i;
        float4 q = *(const float4*)(g_qkv + ((size_t)s * BATCH + b) * EMB + h * HDIM + dg);
        Qt[(dg + 0) * 68 + i] = q.x; Qt[(dg + 1) * 68 + i] = q.y;
        Qt[(dg + 2) * 68 + i] = q.z; Qt[(dg + 3) * 68 + i] = q.w;
    }

    float oacc[4][4] = {};
    for (int kt = 0; kt <= qt; kt++) {
        __syncthreads();
        // Load K/V tile (same data): Kt d-major, Vs j-major
        #pragma unroll
        for (int rr = 0; rr < 4; rr++) {
            int j = lrow + rr * 16;
            int t = kt * 64 + j;
            float4 kv = *(const float4*)(g_qkv + ((size_t)t * BATCH + b) * EMB + h * HDIM + dg);
            Kt[(dg + 0) * 68 + j] = kv.x; Kt[(dg + 1) * 68 + j] = kv.y;
            Kt[(dg + 2) * 68 + j] = kv.z; Kt[(dg + 3) * 68 + j] = kv.w;
            *(float4*)(Vs + j * 68 + dg) = kv;
        }
        __syncthreads();

        // GEMM1: scores
        float sacc[4][4] = {};
        #pragma unroll 8
        for (int d = 0; d < HDIM; d++) {
            float4 ra = *(const float4*)(Qt + d * 68 + tm);
            float4 rb = *(const float4*)(Kt + d * 68 + tn);
            float pa[4] = {ra.x, ra.y, ra.z, ra.w};
            float pb[4] = {rb.x, rb.y, rb.z, rb.w};
            #pragma unroll
            for (int i = 0; i < 4; i++)
                #pragma unroll
                for (int j = 0; j < 4; j++)
                    sacc[i][j] += pa[i] * pb[j];
        }
        // scale + SiLU + causal mask, write W transposed
        bool diag = (kt == qt);
        #pragma unroll
        for (int i = 0; i < 4; i++)
            #pragma unroll
            for (int j = 0; j < 4; j++) {
                float x = sacc[i][j] * 0.125f;
                float w = silu_f(x);
                if (diag && (tn + j) > (tm + i)) w = 0.0f;
                Ws[(tn + j) * 68 + (tm + i)] = w;
            }
        __syncthreads();

        // GEMM2: O += W @ V
        #pragma unroll 8
        for (int j = 0; j < 64; j++) {
            float4 rw = *(const float4*)(Ws + j * 68 + tm);
            float4 rv = *(const float4*)(Vs + j * 68 + tn);
            float pw[4] = {rw.x, rw.y, rw.z, rw.w};
            float pv[4] = {rv.x, rv.y, rv.z, rv.w};
            #pragma unroll
            for (int i = 0; i < 4; i++)
                #pragma unroll
                for (int c = 0; c < 4; c++)
                    oacc[i][c] += pw[i] * pv[c];
        }
    }

    // Write O tile
    #pragma unroll
    for (int i = 0; i < 4; i++) {
        int s = qt * 64 + tm + i;
        #pragma unroll
        for (int c = 0; c < 4; c++)
            g_attn[((size_t)s * BATCH + b) * EMB + h * HDIM + tn + c] = oacc[i][c];
    }
}

// ---------------------------------------------------------------------------
// Kernel 4: out = src + (attn * u) @ Wo^T + bo.  M=4096, N=1024, K=1024.
// ---------------------------------------------------------------------------
__global__ void outproj_kernel(const float* __restrict__ W,
                               const float* __restrict__ bias,
                               const float* __restrict__ src,
                               float* __restrict__ out) {
    __shared__ float As[16][68];
    __shared__ float Bs[16][68];
    int bm = blockIdx.y * 64;
    int bn = blockIdx.x * 64;
    int tid = threadIdx.x;
    int lr = tid >> 2;
    int lc = tid & 3;
    int tm = (tid >> 4) << 2;
    int tn = (tid & 15) << 2;
    float acc[4][4] = {};
    for (int k0 = 0; k0 < EMB; k0 += 16) {
        size_t aoff = (size_t)(bm + lr) * EMB + k0 + lc * 4;
        float4 a1 = *(const float4*)(g_attn + aoff);
        float4 a2 = *(const float4*)(g_u + aoff);
        float4 b = *(const float4*)(W + (size_t)(bn + lr) * EMB + k0 + lc * 4);
        As[lc * 4 + 0][lr] = a1.x * a2.x; As[lc * 4 + 1][lr] = a1.y * a2.y;
        As[lc * 4 + 2][lr] = a1.z * a2.z; As[lc * 4 + 3][lr] = a1.w * a2.w;
        Bs[lc * 4 + 0][lr] = b.x; Bs[lc * 4 + 1][lr] = b.y;
        Bs[lc * 4 + 2][lr] = b.z; Bs[lc * 4 + 3][lr] = b.w;
        __syncthreads();
        #pragma unroll
        for (int k = 0; k < 16; k++) {
            float4 ra = *(const float4*)&As[k][tm];
            float4 rb = *(const float4*)&Bs[k][tn];
            float pa[4] = {ra.x, ra.y, ra.z, ra.w};
            float pb[4] = {rb.x, rb.y, rb.z, rb.w};
            #pragma unroll
            for (int i = 0; i < 4; i++)
                #pragma unroll
                for (int j = 0; j < 4; j++)
                    acc[i][j] += pa[i] * pb[j];
        }
        __syncthreads();
    }
    #pragma unroll
    for (int i = 0; i < 4; i++) {
        int m = bm + tm + i;
        #pragma unroll
        for (int j = 0; j < 4; j++) {
            int n = bn + tn + j;
            out[(size_t)m * EMB + n] = src[(size_t)m * EMB + n] + acc[i][j] + bias[n];
        }
    }
}

// ---------------------------------------------------------------------------
extern "C" void kernel_launch(void* const* d_in, const int* in_sizes, int n_in,
                              void* d_out, int out_size) {
    const float* src   = (const float*)d_in[0];
    // d_in[1] = src_mask (int32 tril) — causal predicate computed directly
    const float* in_w  = (const float*)d_in[2];
    const float* in_b  = (const float*)d_in[3];
    const float* out_w = (const float*)d_in[4];
    const float* out_b = (const float*)d_in[5];
    const float* ln_g  = (const float*)d_in[6];
    const float* ln_b  = (const float*)d_in[7];
    float* out = (float*)d_out;

    const int ATTN_SMEM = 4 * 64 * 68 * (int)sizeof(float);  // 69632 B
    cudaFuncSetAttribute(attn_kernel, cudaFuncAttributeMaxDynamicSharedMemorySize, ATTN_SMEM);

    ln_kernel<<<ROWS, 256>>>(src, ln_g, ln_b);
    inproj_kernel<<<dim3(2 * EMB / 64, ROWS / 64), 256>>>(in_w, in_b);
    attn_kernel<<<dim3(SEQ / 64, BATCH * HEADS), 256, ATTN_SMEM>>>();
    outproj_kernel<<<dim3(EMB / 64, ROWS / 64), 256>>>(out_w, out_b, src, out);
}

// round 5
// speedup vs baseline: 1.4855x; 1.4855x over previous
#include <cuda_runtime.h>
#include <cuda_bf16.h>
#include <math.h>
#include <stdint.h>

// Problem constants
#define SEQ 2048
#define BATCH 2
#define EMB 1024
#define HEADS 16
#define HDIM 64
#define ROWS (SEQ * BATCH)   // 4096

// ---------------------------------------------------------------------------
// Scratch (__device__ globals: allocation-free rule)
// ---------------------------------------------------------------------------
__device__ __align__(16) __nv_bfloat16 g_xn_hi[(size_t)ROWS * EMB];
__device__ __align__(16) __nv_bfloat16 g_xn_lo[(size_t)ROWS * EMB];
__device__ __align__(16) __nv_bfloat16 g_inw_hi[(size_t)2 * EMB * EMB];
__device__ __align__(16) __nv_bfloat16 g_inw_lo[(size_t)2 * EMB * EMB];
__device__ __align__(16) __nv_bfloat16 g_ow_hi[(size_t)EMB * EMB];
__device__ __align__(16) __nv_bfloat16 g_ow_lo[(size_t)EMB * EMB];
__device__ __align__(16) __nv_bfloat16 g_gt_hi[(size_t)ROWS * EMB];
__device__ __align__(16) __nv_bfloat16 g_gt_lo[(size_t)ROWS * EMB];
__device__ float g_qkv[(size_t)ROWS * EMB];
__device__ float g_u[(size_t)ROWS * EMB];
__device__ float g_attn[(size_t)ROWS * EMB];

__device__ __forceinline__ float silu_f(float x) {
    return x / (1.0f + expf(-x));
}

__device__ __forceinline__ uint32_t smem_u32(const void* p) {
    uint32_t a;
    asm("{ .reg .u64 t; cvta.to.shared.u64 t, %1; cvt.u32.u64 %0, t; }" : "=r"(a) : "l"(p));
    return a;
}

// Portable async-copy / ldmatrix / mma (compute_103-safe, sm_80+ ISA)
#define CP16(dst_u32, src_gptr) \
    asm volatile("cp.async.cg.shared.global [%0], [%1], 16;" \
                 :: "r"(dst_u32), "l"(__cvta_generic_to_global(src_gptr)) : "memory")
#define CP_COMMIT() asm volatile("cp.async.commit_group;" ::: "memory")
#define CP_WAIT(N)  asm volatile("cp.async.wait_group %0;" :: "n"(N) : "memory")

__device__ __forceinline__ void ldsm4(uint32_t* r, uint32_t addr) {
    asm volatile("ldmatrix.sync.aligned.m8n8.x4.shared.b16 {%0,%1,%2,%3}, [%4];"
                 : "=r"(r[0]), "=r"(r[1]), "=r"(r[2]), "=r"(r[3]) : "r"(addr));
}
__device__ __forceinline__ void mma16816(float* c, const uint32_t* a,
                                         uint32_t b0, uint32_t b1) {
    asm volatile(
        "mma.sync.aligned.m16n8k16.row.col.f32.bf16.bf16.f32 "
        "{%0,%1,%2,%3}, {%4,%5,%6,%7}, {%8,%9}, {%0,%1,%2,%3};"
        : "+f"(c[0]), "+f"(c[1]), "+f"(c[2]), "+f"(c[3])
        : "r"(a[0]), "r"(a[1]), "r"(a[2]), "r"(a[3]), "r"(b0), "r"(b1));
}

__device__ __forceinline__ void split_bf16(float v, __nv_bfloat16& hi, __nv_bfloat16& lo) {
    hi = __float2bfloat16(v);
    lo = __float2bfloat16(v - __bfloat162float(hi));
}

// ---------------------------------------------------------------------------
// Kernel 1: LayerNorm -> split-bf16 xnorm. One block (256 thr) per row.
// ---------------------------------------------------------------------------
__global__ void ln_kernel(const float* __restrict__ src,
                          const float* __restrict__ gamma,
                          const float* __restrict__ beta) {
    int row = blockIdx.x;
    int t = threadIdx.x;
    const float4* x4 = (const float4*)(src + (size_t)row * EMB);
    float4 v = x4[t];
    float s = v.x + v.y + v.z + v.w;
    float q = v.x * v.x + v.y * v.y + v.z * v.z + v.w * v.w;
    #pragma unroll
    for (int o = 16; o > 0; o >>= 1) {
        s += __shfl_xor_sync(0xFFFFFFFFu, s, o);
        q += __shfl_xor_sync(0xFFFFFFFFu, q, o);
    }
    __shared__ float ss[8], sq[8];
    int w = t >> 5, l = t & 31;
    if (l == 0) { ss[w] = s; sq[w] = q; }
    __syncthreads();
    float st = 0.f, qt = 0.f;
    #pragma unroll
    for (int i = 0; i < 8; i++) { st += ss[i]; qt += sq[i]; }
    float mu = st * (1.0f / EMB);
    float var = qt * (1.0f / EMB) - mu * mu;
    float inv = rsqrtf(var + 1e-5f);
    float4 gg = ((const float4*)gamma)[t];
    float4 bb = ((const float4*)beta)[t];
    float o[4];
    o[0] = (v.x - mu) * inv * gg.x + bb.x;
    o[1] = (v.y - mu) * inv * gg.y + bb.y;
    o[2] = (v.z - mu) * inv * gg.z + bb.z;
    o[3] = (v.w - mu) * inv * gg.w + bb.w;
    size_t base = (size_t)row * EMB + t * 4;
    #pragma unroll
    for (int e = 0; e < 4; e++) {
        __nv_bfloat16 hi, lo;
        split_bf16(o[e], hi, lo);
        g_xn_hi[base + e] = hi;
        g_xn_lo[base + e] = lo;
    }
}

// ---------------------------------------------------------------------------
// Kernel 2: convert in_proj_w + out_proj_w fp32 -> split bf16
// ---------------------------------------------------------------------------
__global__ void wconv_kernel(const float* __restrict__ inw,
                             const float* __restrict__ outw) {
    const size_t N1 = (size_t)2 * EMB * EMB / 4;
    const size_t N2 = (size_t)EMB * EMB / 4;
    size_t i = (size_t)blockIdx.x * blockDim.x + threadIdx.x;
    if (i < N1) {
        float4 v = ((const float4*)inw)[i];
        float f[4] = {v.x, v.y, v.z, v.w};
        #pragma unroll
        for (int e = 0; e < 4; e++) {
            __nv_bfloat16 hi, lo;
            split_bf16(f[e], hi, lo);
            g_inw_hi[i * 4 + e] = hi;
            g_inw_lo[i * 4 + e] = lo;
        }
    } else if (i < N1 + N2) {
        size_t j = i - N1;
        float4 v = ((const float4*)outw)[j];
        float f[4] = {v.x, v.y, v.z, v.w};
        #pragma unroll
        for (int e = 0; e < 4; e++) {
            __nv_bfloat16 hi, lo;
            split_bf16(f[e], hi, lo);
            g_ow_hi[j * 4 + e] = hi;
            g_ow_lo[j * 4 + e] = lo;
        }
    }
}

// ---------------------------------------------------------------------------
// Kernel 5: gated = attn * u -> split bf16 (A operand of out_proj)
// ---------------------------------------------------------------------------
__global__ void gated_kernel() {
    size_t i = (size_t)blockIdx.x * blockDim.x + threadIdx.x;
    float4 a = ((const float4*)g_attn)[i];
    float4 u = ((const float4*)g_u)[i];
    float f[4] = {a.x * u.x, a.y * u.y, a.z * u.z, a.w * u.w};
    #pragma unroll
    for (int e = 0; e < 4; e++) {
        __nv_bfloat16 hi, lo;
        split_bf16(f[e], hi, lo);
        g_gt_hi[i * 4 + e] = hi;
        g_gt_lo[i * 4 + e] = lo;
    }
}

// ---------------------------------------------------------------------------
// Split-bf16 GEMM via mma.sync:  C[M,N] = A[M,K] @ B[N,K]^T   (3-pass split)
// Block 128x128, BK=32, 8 warps (warp tile 32x64), 4-stage cp.async pipeline.
// Smem per stage: Ahi|Alo|Bhi|Blo, each 128 rows x 64B, XOR-swizzled.
// MODE 0 = in_proj (bias+silu -> qkv/u); MODE 1 = out_proj (src+bias -> out)
// ---------------------------------------------------------------------------
#define BK 32
#define NKS (EMB / BK)          // 32
#define STG_BYTES 32768
#define SUB_A_HI 0
#define SUB_A_LO 8192
#define SUB_B_HI 16384
#define SUB_B_LO 24576
#define GEMM_SMEM (4 * STG_BYTES)   // 131072

__device__ __forceinline__ void stage_load(uint32_t sdst,
                                           const __nv_bfloat16* __restrict__ Ahi,
                                           const __nv_bfloat16* __restrict__ Alo,
                                           const __nv_bfloat16* __restrict__ Bhi,
                                           const __nv_bfloat16* __restrict__ Blo,
                                           int bm, int bn, int k0, int tid) {
    #pragma unroll
    for (int t = 0; t < 2; t++) {
        int idx = tid + t * 256;            // 0..511
        int row = idx >> 2, seg = idx & 3;  // 128 rows x 4 x 16B
        uint32_t soff = row * 64 + ((seg ^ ((row >> 1) & 3)) << 4);
        size_t ga = (size_t)(bm + row) * EMB + k0 + seg * 8;
        size_t gb = (size_t)(bn + row) * EMB + k0 + seg * 8;
        CP16(sdst + SUB_A_HI + soff, Ahi + ga);
        CP16(sdst + SUB_A_LO + soff, Alo + ga);
        CP16(sdst + SUB_B_HI + soff, Bhi + gb);
        CP16(sdst + SUB_B_LO + soff, Blo + gb);
    }
}

template <int MODE>
__global__ __launch_bounds__(256, 1)
void gemm_mma_kernel(const float* __restrict__ bias,
                     const float* __restrict__ src,
                     float* __restrict__ out) {
    extern __shared__ char smem[];
    uint32_t sb = smem_u32(smem);
    int tid = threadIdx.x, warp = tid >> 5, lane = tid & 31;
    int bn = blockIdx.x * 128, bm = blockIdx.y * 128;

    const __nv_bfloat16 *Ahi, *Alo, *Bhi, *Blo;
    if (MODE == 0) { Ahi = g_xn_hi; Alo = g_xn_lo; Bhi = g_inw_hi; Blo = g_inw_lo; }
    else           { Ahi = g_gt_hi; Alo = g_gt_lo; Bhi = g_ow_hi;  Blo = g_ow_lo; }

    // prologue: stages 0..2
    #pragma unroll
    for (int s = 0; s < 3; s++) {
        stage_load(sb + s * STG_BYTES, Ahi, Alo, Bhi, Blo, bm, bn, s * BK, tid);
        CP_COMMIT();
    }

    int wm = (warp >> 1) * 32;   // warp M origin (4 m-warps)
    int wn = (warp & 1) * 64;    // warp N origin (2 n-warps)
    int lrow = lane & 15;        // ldmatrix row-within-16
    int lseg = lane >> 4;        // ldmatrix seg select (k half)

    float acc[2][8][4];
    #pragma unroll
    for (int a = 0; a < 2; a++)
        #pragma unroll
        for (int b = 0; b < 8; b++)
            #pragma unroll
            for (int c = 0; c < 4; c++) acc[a][b][c] = 0.f;

    for (int kt = 0; kt < NKS; kt++) {
        CP_WAIT(2);
        __syncthreads();
        uint32_t st = sb + (kt & 3) * STG_BYTES;
        if (kt + 3 < NKS) {
            stage_load(sb + ((kt + 3) & 3) * STG_BYTES, Ahi, Alo, Bhi, Blo,
                       bm, bn, (kt + 3) * BK, tid);
            CP_COMMIT();
        }
        #pragma unroll
        for (int kk = 0; kk < 2; kk++) {       // two k16 halves of BK=32
            int seg = kk * 2 + lseg;
            uint32_t ahi[2][4], alo[2][4];
            #pragma unroll
            for (int mt = 0; mt < 2; mt++) {
                int r = wm + mt * 16 + lrow;
                uint32_t off = r * 64 + ((seg ^ ((r >> 1) & 3)) << 4);
                ldsm4(ahi[mt], st + SUB_A_HI + off);
                ldsm4(alo[mt], st + SUB_A_LO + off);
            }
            uint32_t bhi[4][4], blo[4][4];
            #pragma unroll
            for (int p = 0; p < 4; p++) {
                int r = wn + p * 16 + lrow;
                uint32_t off = r * 64 + ((seg ^ ((r >> 1) & 3)) << 4);
                ldsm4(bhi[p], st + SUB_B_HI + off);
                ldsm4(blo[p], st + SUB_B_LO + off);
            }
            #pragma unroll
            for (int mt = 0; mt < 2; mt++)
                #pragma unroll
                for (int p = 0; p < 4; p++) {
                    mma16816(acc[mt][2 * p],     ahi[mt], bhi[p][0], bhi[p][2]);
                    mma16816(acc[mt][2 * p],     ahi[mt], blo[p][0], blo[p][2]);
                    mma16816(acc[mt][2 * p],     alo[mt], bhi[p][0], bhi[p][2]);
                    mma16816(acc[mt][2 * p + 1], ahi[mt], bhi[p][1], bhi[p][3]);
                    mma16816(acc[mt][2 * p + 1], ahi[mt], blo[p][1], blo[p][3]);
                    mma16816(acc[mt][2 * p + 1], alo[mt], bhi[p][1], bhi[p][3]);
                }
        }
    }

    // Epilogue from register fragments.
    int r0 = bm + wm + (lane >> 2);
    int c0 = bn + wn + 2 * (lane & 3);
    #pragma unroll
    for (int mt = 0; mt < 2; mt++) {
        #pragma unroll
        for (int nt = 0; nt < 8; nt++) {
            int col = c0 + nt * 8;
            float* a = acc[mt][nt];
            int r = r0 + mt * 16;
            if (MODE == 0) {
                float b0 = bias[col], b1 = bias[col + 1];
                float v0 = silu_f(a[0] + b0);
                float v1 = silu_f(a[1] + b1);
                float v2 = silu_f(a[2] + b0);
                float v3 = silu_f(a[3] + b1);
                if (bn < EMB) {
                    *(float2*)&g_qkv[(size_t)r * EMB + col]       = make_float2(v0, v1);
                    *(float2*)&g_qkv[(size_t)(r + 8) * EMB + col] = make_float2(v2, v3);
                } else {
                    int cc = col - EMB;
                    *(float2*)&g_u[(size_t)r * EMB + cc]       = make_float2(v0, v1);
                    *(float2*)&g_u[(size_t)(r + 8) * EMB + cc] = make_float2(v2, v3);
                }
            } else {
                float b0 = bias[col], b1 = bias[col + 1];
                float2 s0 = *(const float2*)&src[(size_t)r * EMB + col];
                float2 s1 = *(const float2*)&src[(size_t)(r + 8) * EMB + col];
                *(float2*)&out[(size_t)r * EMB + col] =
                    make_float2(s0.x + a[0] + b0, s0.y + a[1] + b1);
                *(float2*)&out[(size_t)(r + 8) * EMB + col] =
                    make_float2(s1.x + a[2] + b0, s1.y + a[3] + b1);
            }
        }
    }
}

// ---------------------------------------------------------------------------
// Kernel 4: fused causal SiLU-attention (fp32 SIMT — unchanged this round).
// ---------------------------------------------------------------------------
__global__ void attn_kernel() {
    extern __shared__ float fsm[];
    float* Qt = fsm;                  // [64][68] d-major
    float* Kt = Qt + 64 * 68;         // [64][68] d-major
    float* Vs = Kt + 64 * 68;         // [64][68] j-major
    float* Ws = Vs + 64 * 68;         // [64][68] j-major (W transposed)

    int qt = blockIdx.x;
    int bh = blockIdx.y;
    int b = bh >> 4, h = bh & 15;
    int tid = threadIdx.x;
    int tm = (tid >> 4) << 2;
    int tn = (tid & 15) << 2;
    int lrow = tid >> 4;
    int dg = (tid & 15) << 2;

    #pragma unroll
    for (int rr = 0; rr < 4; rr++) {
        int i = lrow + rr * 16;
        int s = qt * 64 + i;
        float4 q = *(const float4*)(g_qkv + ((size_t)s * BATCH + b) * EMB + h * HDIM + dg);
        Qt[(dg + 0) * 68 + i] = q.x; Qt[(dg + 1) * 68 + i] = q.y;
        Qt[(dg + 2) * 68 + i] = q.z; Qt[(dg + 3) * 68 + i] = q.w;
    }

    float oacc[4][4] = {};
    for (int kt = 0; kt <= qt; kt++) {
        __syncthreads();
        #pragma unroll
        for (int rr = 0; rr < 4; rr++) {
            int j = lrow + rr * 16;
            int t = kt * 64 + j;
            float4 kv = *(const float4*)(g_qkv + ((size_t)t * BATCH + b) * EMB + h * HDIM + dg);
            Kt[(dg + 0) * 68 + j] = kv.x; Kt[(dg + 1) * 68 + j] = kv.y;
            Kt[(dg + 2) * 68 + j] = kv.z; Kt[(dg + 3) * 68 + j] = kv.w;
            *(float4*)(Vs + j * 68 + dg) = kv;
        }
        __syncthreads();

        float sacc[4][4] = {};
        #pragma unroll 8
        for (int d = 0; d < HDIM; d++) {
            float4 ra = *(const float4*)(Qt + d * 68 + tm);
            float4 rb = *(const float4*)(Kt + d * 68 + tn);
            float pa[4] = {ra.x, ra.y, ra.z, ra.w};
            float pb[4] = {rb.x, rb.y, rb.z, rb.w};
            #pragma unroll
            for (int i2 = 0; i2 < 4; i2++)
                #pragma unroll
                for (int j2 = 0; j2 < 4; j2++)
                    sacc[i2][j2] += pa[i2] * pb[j2];
        }
        bool diag = (kt == qt);
        #pragma unroll
        for (int i2 = 0; i2 < 4; i2++)
            #pragma unroll
            for (int j2 = 0; j2 < 4; j2++) {
                float x = sacc[i2][j2] * 0.125f;
                float w = silu_f(x);
                if (diag && (tn + j2) > (tm + i2)) w = 0.0f;
                Ws[(tn + j2) * 68 + (tm + i2)] = w;
            }
        __syncthreads();

        #pragma unroll 8
        for (int j2 = 0; j2 < 64; j2++) {
            float4 rw = *(const float4*)(Ws + j2 * 68 + tm);
            float4 rv = *(const float4*)(Vs + j2 * 68 + tn);
            float pw[4] = {rw.x, rw.y, rw.z, rw.w};
            float pv[4] = {rv.x, rv.y, rv.z, rv.w};
            #pragma unroll
            for (int i2 = 0; i2 < 4; i2++)
                #pragma unroll
                for (int c = 0; c < 4; c++)
                    oacc[i2][c] += pw[i2] * pv[c];
        }
    }

    #pragma unroll
    for (int i2 = 0; i2 < 4; i2++) {
        int s = qt * 64 + tm + i2;
        #pragma unroll
        for (int c = 0; c < 4; c++)
            g_attn[((size_t)s * BATCH + b) * EMB + h * HDIM + tn + c] = oacc[i2][c];
    }
}

// ---------------------------------------------------------------------------
extern "C" void kernel_launch(void* const* d_in, const int* in_sizes, int n_in,
                              void* d_out, int out_size) {
    const float* src   = (const float*)d_in[0];
    // d_in[1] = src_mask (causal tril) — predicate computed directly
    const float* in_w  = (const float*)d_in[2];
    const float* in_b  = (const float*)d_in[3];
    const float* out_w = (const float*)d_in[4];
    const float* out_b = (const float*)d_in[5];
    const float* ln_g  = (const float*)d_in[6];
    const float* ln_b  = (const float*)d_in[7];
    float* out = (float*)d_out;

    const int ATTN_SMEM = 4 * 64 * 68 * (int)sizeof(float);  // 69632 B
    cudaFuncSetAttribute(attn_kernel, cudaFuncAttributeMaxDynamicSharedMemorySize, ATTN_SMEM);
    cudaFuncSetAttribute(gemm_mma_kernel<0>, cudaFuncAttributeMaxDynamicSharedMemorySize, GEMM_SMEM);
    cudaFuncSetAttribute(gemm_mma_kernel<1>, cudaFuncAttributeMaxDynamicSharedMemorySize, GEMM_SMEM);

    ln_kernel<<<ROWS, 256>>>(src, ln_g, ln_b);
    wconv_kernel<<<3072, 256>>>(in_w, out_w);
    gemm_mma_kernel<0><<<dim3(2 * EMB / 128, ROWS / 128), 256, GEMM_SMEM>>>(
        in_b, nullptr, nullptr);
    attn_kernel<<<dim3(SEQ / 64, BATCH * HEADS), 256, ATTN_SMEM>>>();
    gated_kernel<<<4096, 256>>>();
    gemm_mma_kernel<1><<<dim3(EMB / 128, ROWS / 128), 256, GEMM_SMEM>>>(
        out_b, src, out);
}